// round 11
// baseline (speedup 1.0000x reference)
#include <cuda_runtime.h>
#include <cstdint>

// Problem constants
#define B_   32
#define C_   256
#define H_   58
#define W_   58
#define OC_  256
#define KH_  3
#define KW_  3
#define HO_  56
#define WO_  56
#define HW_  (H_*W_)            // 3364
#define NWORDS 8                // 256 channels / 32 bits
#define CN_  2304               // C*KH*KW
#define NINPUT 861184.0f        // C*H*W (alpha normalizer)

// Scratch (device globals; no allocations allowed)
__device__ unsigned g_xpack[B_ * HW_ * NWORDS];        // [b][y][x][w]  3.44 MB
__device__ unsigned g_wpack[OC_ * KH_ * KW_ * NWORDS]; // [o][k][w]     73.7 KB
__device__ float    g_alpha[OC_];

// Forced single-LOP3 3-input ops
template <int LUT>
__device__ __forceinline__ unsigned lop3(unsigned a, unsigned b, unsigned c) {
    unsigned r;
    asm("lop3.b32 %0, %1, %2, %3, %4;" : "=r"(r) : "r"(a), "r"(b), "r"(c), "n"(LUT));
    return r;
}
#define XOR3(a,b,c)  lop3<0x96>(a,b,c)                 // a^b^c
#define MAJ3(a,b,c)  lop3<0xE8>(a,b,c)                 // majority
#define MAJU(x,y,u)  lop3<0xD4>(x,y,u)                 // (x&y)|((x^y)&~u)

// ---------------------------------------------------------------------------
// Fused pack kernel. 1D grid of 2048 blocks x 256 threads:
//   blocks [0,1792): pack activations, 2 positions per thread, high MLP
//   blocks [1792,2048): pack weights (ballot) + alpha
// ---------------------------------------------------------------------------
#define XBLOCKS (B_ * NWORDS * 7)   // 1792

__global__ void __launch_bounds__(256) pack_kernel(const float* __restrict__ x,
                                                   const float* __restrict__ wgt) {
    int blk = blockIdx.x;
    if (blk < XBLOCKS) {
        int b    = blk / 56;
        int rem  = blk % 56;
        int w    = rem / 7;
        int pblk = rem % 7;
        int pos0 = pblk * 512 + threadIdx.x;

        const float* xp = x + ((size_t)(b * C_ + w * 32) * HW_);
        float v0[32], v1[32];
        bool ok0 = pos0 < HW_;
        bool ok1 = pos0 + 256 < HW_;
#pragma unroll
        for (int c = 0; c < 32; c++) {
            size_t off = (size_t)c * HW_;
            v0[c] = ok0 ? __ldg(xp + off + pos0)       : 0.f;
            v1[c] = ok1 ? __ldg(xp + off + pos0 + 256) : 0.f;
        }
        unsigned bits0 = 0, bits1 = 0;
#pragma unroll
        for (int c = 0; c < 32; c++) {
            bits0 |= (v0[c] > 0.5f ? 1u : 0u) << c;
            bits1 |= (v1[c] > 0.5f ? 1u : 0u) << c;
        }
        if (ok0) g_xpack[((size_t)b * HW_ + pos0) * NWORDS + w] = bits0;
        if (ok1) g_xpack[((size_t)b * HW_ + pos0 + 256) * NWORDS + w] = bits1;
    } else {
        int o = blk - XBLOCKS;
        int c = threadIdx.x;
        int lane = c & 31;
        int wrp  = c >> 5;

        const float* wp = wgt + (size_t)(o * C_ + c) * (KH_ * KW_);
        float asum = 0.f;
#pragma unroll
        for (int k = 0; k < KH_ * KW_; k++) {
            float v = wp[k];
            asum += fabsf(v);
            unsigned word = __ballot_sync(0xffffffffu, v >= 0.f);
            if (lane == 0) g_wpack[(o * 9 + k) * NWORDS + wrp] = word;
        }

        __shared__ float red[256];
        red[c] = asum;
        __syncthreads();
#pragma unroll
        for (int s = 128; s > 0; s >>= 1) {
            if (c < s) red[c] += red[c + s];
            __syncthreads();
        }
        if (c == 0) g_alpha[o] = red[0] / NINPUT;
    }
}

// ---------------------------------------------------------------------------
// Conv: two-level CSA XNOR conv, ONE output per iteration (low live-reg set),
// <=128 regs -> 4 CTAs/SM (16 warps), fma-pipe epilogue.
// grid = (B_*HO_, 2), block = 128 (thread = output channel within half).
// ---------------------------------------------------------------------------
__global__ void __launch_bounds__(128, 4)
xnor_conv_kernel(float* __restrict__ out) {
    int by = blockIdx.x;
    int b  = by / HO_;
    int y  = by % HO_;
    int o  = blockIdx.y * 128 + threadIdx.x;
    int t  = threadIdx.x;

    __shared__ __align__(16) unsigned sx[3 * W_  * NWORDS];  // 5568 B
    __shared__ __align__(16) unsigned s3[3 * WO_ * NWORDS];  // 5376 B

    // load 3 packed rows
    const int ROW4 = W_ * NWORDS / 4; // 116 uint4 per row
    for (int i = t; i < 3 * ROW4; i += 128) {
        int kh = i / ROW4;
        int r  = i - kh * ROW4;
        const uint4* src = (const uint4*)(g_xpack + ((size_t)(b * H_ + y + kh) * W_) * NWORDS);
        ((uint4*)sx)[kh * ROW4 + r] = src[r];
    }

    // per-thread weights: w0, w1 (kw taps 0,1) and wx3 = w0^w1^w2, [kh*8+w]
    unsigned w0[24], w1[24], wx3[24];
    {
        const uint4* wp4 = (const uint4*)(g_wpack + (size_t)o * 72);
#pragma unroll
        for (int kh = 0; kh < 3; kh++) {
            uint4 a0 = wp4[(kh * 3 + 0) * 2], a1 = wp4[(kh * 3 + 0) * 2 + 1];
            uint4 b0 = wp4[(kh * 3 + 1) * 2], b1 = wp4[(kh * 3 + 1) * 2 + 1];
            uint4 c0 = wp4[(kh * 3 + 2) * 2], c1 = wp4[(kh * 3 + 2) * 2 + 1];
            ((uint4*)w0)[kh * 2] = a0; ((uint4*)w0)[kh * 2 + 1] = a1;
            ((uint4*)w1)[kh * 2] = b0; ((uint4*)w1)[kh * 2 + 1] = b1;
            wx3[kh * 8 + 0] = a0.x ^ b0.x ^ c0.x;
            wx3[kh * 8 + 1] = a0.y ^ b0.y ^ c0.y;
            wx3[kh * 8 + 2] = a0.z ^ b0.z ^ c0.z;
            wx3[kh * 8 + 3] = a0.w ^ b0.w ^ c0.w;
            wx3[kh * 8 + 4] = a1.x ^ b1.x ^ c1.x;
            wx3[kh * 8 + 5] = a1.y ^ b1.y ^ c1.y;
            wx3[kh * 8 + 6] = a1.z ^ b1.z ^ c1.z;
            wx3[kh * 8 + 7] = a1.w ^ b1.w ^ c1.w;
        }
    }
    float a = g_alpha[o];
    float base = a * (float)CN_;     // out = base + na * P
    float na   = -2.0f * a;
    __syncthreads();

    // s3[kh][c][w] = sx[kh][c] ^ sx[kh][c+1] ^ sx[kh][c+2]
    for (int i = t; i < 3 * WO_ * NWORDS; i += 128) {
        int kh = i / (WO_ * NWORDS);
        int r  = i - kh * (WO_ * NWORDS);
        int bidx = kh * (W_ * NWORDS) + r;
        s3[i] = XOR3(sx[bidx], sx[bidx + NWORDS], sx[bidx + 2 * NWORDS]);
    }
    __syncthreads();

    float* outp = out + ((size_t)(b * OC_ + o) * HO_ + y) * WO_;

#pragma unroll 1
    for (int x0 = 0; x0 < WO_; x0++) {
        int Su = 0, Cu = 0, Sv = 0, Cv = 0;
#pragma unroll
        for (int half = 0; half < 2; half++) {
            unsigned u[3][4], v[3][4];          // [kh][j]
#pragma unroll
            for (int kh = 0; kh < 3; kh++) {
                const unsigned* rp = &sx[(kh * W_ + x0) * NWORDS + half * 4];
                uint4 q0 = *(const uint4*)(rp);
                uint4 q1 = *(const uint4*)(rp + NWORDS);
                uint4 t0 = *(const uint4*)(&s3[(kh * WO_ + x0) * NWORDS + half * 4]);
                unsigned p0[4] = {q0.x, q0.y, q0.z, q0.w};
                unsigned p1[4] = {q1.x, q1.y, q1.z, q1.w};
                unsigned s0[4] = {t0.x, t0.y, t0.z, t0.w};
#pragma unroll
                for (int j = 0; j < 4; j++) {
                    int wi = kh * 8 + half * 4 + j;
                    unsigned uu = s0[j] ^ wx3[wi];
                    u[kh][j] = uu;
                    v[kh][j] = MAJU(p0[j] ^ w0[wi], p1[j] ^ w1[wi], uu);
                }
            }
#pragma unroll
            for (int j = 0; j < 4; j++) {
                Su += __popc(XOR3(u[0][j], u[1][j], u[2][j]));
                Cu += __popc(MAJ3(u[0][j], u[1][j], u[2][j]));
                Sv += __popc(XOR3(v[0][j], v[1][j], v[2][j]));
                Cv += __popc(MAJ3(v[0][j], v[1][j], v[2][j]));
            }
        }
        int P = Su + ((Cu + Sv) << 1) + (Cv << 2);
        outp[x0] = fmaf(na, (float)P, base);
    }
}

// ---------------------------------------------------------------------------
extern "C" void kernel_launch(void* const* d_in, const int* in_sizes, int n_in,
                              void* d_out, int out_size) {
    const float* x   = (const float*)d_in[0];
    const float* wgt = (const float*)d_in[1];
    float* out = (float*)d_out;

    pack_kernel<<<XBLOCKS + OC_, 256>>>(x, wgt);
    dim3 g3(B_ * HO_, 2);
    xnor_conv_kernel<<<g3, 128>>>(out);
}